// round 2
// baseline (speedup 1.0000x reference)
#include <cuda_runtime.h>

// WavUnPacking: inverse Haar DWT (db1, per-2x2 butterfly + interleave).
// x: (B=8, C=256, H=128, W=128) fp32 -> out: (B=8, C4=64, 2H=256, 2W=256) fp32
//
// R2: 8 floats (2x float4) per operand per thread -> MLP_p1=8 front-batched
// LDG.128; streaming cache hints (__ldcs/__stcs) since data is touch-once.

static constexpr int B  = 8;
static constexpr int C4 = 64;      // output channels
static constexpr int H  = 128;
static constexpr int W4 = 128 / 4; // float4s per input row = 32
static constexpr int W8 = W4 / 2;  // pairs of float4 per row = 16

__device__ __forceinline__ void butterfly(const float4& ll, const float4& lh,
                                          const float4& hl, const float4& hh,
                                          float4& e00, float4& e01,
                                          float4& e10, float4& e11)
{
    float a, b, c, d;
    a = ll.x; b = lh.x; c = hl.x; d = hh.x;
    e00.x = 0.5f*(a+b+c+d); e01.x = 0.5f*(a+b-c-d);
    e10.x = 0.5f*(a-b+c-d); e11.x = 0.5f*(a-b-c+d);
    a = ll.y; b = lh.y; c = hl.y; d = hh.y;
    e00.y = 0.5f*(a+b+c+d); e01.y = 0.5f*(a+b-c-d);
    e10.y = 0.5f*(a-b+c-d); e11.y = 0.5f*(a-b-c+d);
    a = ll.z; b = lh.z; c = hl.z; d = hh.z;
    e00.z = 0.5f*(a+b+c+d); e01.z = 0.5f*(a+b-c-d);
    e10.z = 0.5f*(a-b+c-d); e11.z = 0.5f*(a-b-c+d);
    a = ll.w; b = lh.w; c = hl.w; d = hh.w;
    e00.w = 0.5f*(a+b+c+d); e01.w = 0.5f*(a+b-c-d);
    e10.w = 0.5f*(a-b+c-d); e11.w = 0.5f*(a-b-c+d);
}

__global__ void __launch_bounds__(256)
wav_unpack_kernel(const float4* __restrict__ x, float4* __restrict__ out)
{
    int idx = blockIdx.x * blockDim.x + threadIdx.x;
    // idx layout: [b (8)][c (64)][h (128)][w8 (16)]
    int w8 = idx & (W8 - 1);          // 0..15
    int h  = (idx >> 4) & (H - 1);    // 0..127
    int bc = idx >> 11;               // b*64 + c, 0..511
    int b  = bc >> 6;
    int c  = bc & (C4 - 1);

    const int plane = H * W4;                    // 4096 float4 per channel
    int base = ((b * 256 + c) * H + h) * W4 + 2 * w8;
    const int cs = C4 * plane;                   // subband stride in float4

    // 8 front-batched independent loads (MLP_p1 = 8)
    float4 ll0 = __ldcs(&x[base]);
    float4 ll1 = __ldcs(&x[base + 1]);
    float4 lh0 = __ldcs(&x[base + cs]);
    float4 lh1 = __ldcs(&x[base + cs + 1]);
    float4 hl0 = __ldcs(&x[base + 2 * cs]);
    float4 hl1 = __ldcs(&x[base + 2 * cs + 1]);
    float4 hh0 = __ldcs(&x[base + 3 * cs]);
    float4 hh1 = __ldcs(&x[base + 3 * cs + 1]);

    float4 e00, e01, e10, e11;

    // output plane: 256 rows * 64 float4/row per (b,c).
    int otop = (bc * 256 + 2 * h) * 64 + 4 * w8;

    butterfly(ll0, lh0, hl0, hh0, e00, e01, e10, e11);
    __stcs(&out[otop],      make_float4(e00.x, e01.x, e00.y, e01.y));
    __stcs(&out[otop + 1],  make_float4(e00.z, e01.z, e00.w, e01.w));
    __stcs(&out[otop + 64], make_float4(e10.x, e11.x, e10.y, e11.y));
    __stcs(&out[otop + 65], make_float4(e10.z, e11.z, e10.w, e11.w));

    butterfly(ll1, lh1, hl1, hh1, e00, e01, e10, e11);
    __stcs(&out[otop + 2],  make_float4(e00.x, e01.x, e00.y, e01.y));
    __stcs(&out[otop + 3],  make_float4(e00.z, e01.z, e00.w, e01.w));
    __stcs(&out[otop + 66], make_float4(e10.x, e11.x, e10.y, e11.y));
    __stcs(&out[otop + 67], make_float4(e10.z, e11.z, e10.w, e11.w));
}

extern "C" void kernel_launch(void* const* d_in, const int* in_sizes, int n_in,
                              void* d_out, int out_size)
{
    const float4* x = (const float4*)d_in[0];
    float4* out = (float4*)d_out;

    int total_threads = B * C4 * H * W8; // 8*64*128*16 = 1,048,576
    int block = 256;
    int grid = total_threads / block;    // 4096
    wav_unpack_kernel<<<grid, block>>>(x, out);
}

// round 3
// speedup vs baseline: 1.0914x; 1.0914x over previous
#include <cuda_runtime.h>

// WavUnPacking: inverse Haar DWT (db1, per-2x2 butterfly + interleave).
// x: (B=8, C=256, H=128, W=128) fp32 -> out: (B=8, C4=64, 2H=256, 2W=256) fp32
//
// R3: R1 granularity (1 float4 per operand per thread, 32 regs, max occupancy)
// + streaming cache hints (touch-once data, evict-first) + block=512.

static constexpr int B  = 8;
static constexpr int C4 = 64;      // output channels
static constexpr int H  = 128;
static constexpr int W4 = 128 / 4; // float4s per input row = 32

__global__ void __launch_bounds__(512)
wav_unpack_kernel(const float4* __restrict__ x, float4* __restrict__ out)
{
    int idx = blockIdx.x * blockDim.x + threadIdx.x;
    // idx layout: [b (8)][c (64)][h (128)][w4 (32)]
    int w4 = idx & (W4 - 1);          // 0..31
    int h  = (idx >> 5) & (H - 1);    // 0..127
    int bc = idx >> 12;               // b*64 + c, 0..511
    int b  = bc >> 6;
    int c  = bc & (C4 - 1);

    const int plane = H * W4;                 // 4096 float4 per channel
    int base = ((b * 256 + c) * H + h) * W4 + w4;
    const int cs = C4 * plane;                // subband stride in float4

    // 4 front-batched independent streaming loads
    float4 ll = __ldcs(&x[base]);
    float4 lh = __ldcs(&x[base + cs]);
    float4 hl = __ldcs(&x[base + 2 * cs]);
    float4 hh = __ldcs(&x[base + 3 * cs]);

    float4 e00, e01, e10, e11;
    {
        float a, bb, cc, d;
        a = ll.x; bb = lh.x; cc = hl.x; d = hh.x;
        e00.x = 0.5f*(a+bb+cc+d); e01.x = 0.5f*(a+bb-cc-d);
        e10.x = 0.5f*(a-bb+cc-d); e11.x = 0.5f*(a-bb-cc+d);
        a = ll.y; bb = lh.y; cc = hl.y; d = hh.y;
        e00.y = 0.5f*(a+bb+cc+d); e01.y = 0.5f*(a+bb-cc-d);
        e10.y = 0.5f*(a-bb+cc-d); e11.y = 0.5f*(a-bb-cc+d);
        a = ll.z; bb = lh.z; cc = hl.z; d = hh.z;
        e00.z = 0.5f*(a+bb+cc+d); e01.z = 0.5f*(a+bb-cc-d);
        e10.z = 0.5f*(a-bb+cc-d); e11.z = 0.5f*(a-bb-cc+d);
        a = ll.w; bb = lh.w; cc = hl.w; d = hh.w;
        e00.w = 0.5f*(a+bb+cc+d); e01.w = 0.5f*(a+bb-cc-d);
        e10.w = 0.5f*(a-bb+cc-d); e11.w = 0.5f*(a-bb-cc+d);
    }

    // output: 256 rows * 64 float4/row per (b,c) plane.
    int otop = (bc * 256 + 2 * h) * 64 + 2 * w4;
    __stcs(&out[otop],      make_float4(e00.x, e01.x, e00.y, e01.y));
    __stcs(&out[otop + 1],  make_float4(e00.z, e01.z, e00.w, e01.w));
    __stcs(&out[otop + 64], make_float4(e10.x, e11.x, e10.y, e11.y));
    __stcs(&out[otop + 65], make_float4(e10.z, e11.z, e10.w, e11.w));
}

extern "C" void kernel_launch(void* const* d_in, const int* in_sizes, int n_in,
                              void* d_out, int out_size)
{
    const float4* x = (const float4*)d_in[0];
    float4* out = (float4*)d_out;

    int total_threads = B * C4 * H * W4; // 2,097,152
    int block = 512;
    int grid = total_threads / block;    // 4096
    wav_unpack_kernel<<<grid, block>>>(x, out);
}

// round 4
// speedup vs baseline: 1.1880x; 1.0885x over previous
#include <cuda_runtime.h>

// WavUnPacking: inverse Haar DWT (db1, per-2x2 butterfly + interleave).
// x: (B=8, C=256, H=128, W=128) fp32 -> out: (B=8, C4=64, 2H=256, 2W=256) fp32
//
// R4: thread-per-output-float4-column mapping.
//  - Each thread owns output f4 column j (0..63) of one output row-pair:
//    loads float2 (w=2j,2j+1) from each of the 4 subbands (LDG.64, dense
//    256B per warp instruction), stores 2 fully-dense STG.128 (512B per
//    warp instruction, 4 lines). This halves store L1 wavefronts vs the
//    previous stride-2 store pattern.

static constexpr int B  = 8;
static constexpr int C4 = 64;   // output channels
static constexpr int H  = 128;
static constexpr int J  = 64;   // output float4 columns per row (256 floats / 4)

__global__ void __launch_bounds__(256)
wav_unpack_kernel(const float2* __restrict__ x, float4* __restrict__ out)
{
    int idx = blockIdx.x * blockDim.x + threadIdx.x;
    // idx layout: [bc (512)][h (128)][j (64)]
    int j  = idx & (J - 1);           // 0..63 output f4 column
    int h  = (idx >> 6) & (H - 1);    // 0..127
    int bc = idx >> 13;               // 0..511
    int b  = bc >> 6;
    int c  = bc & (C4 - 1);

    // input as float2: per-channel plane = 128 rows * 64 float2 = 8192
    const int plane2 = H * 64;
    int base = ((b * 256 + c) * H + h) * 64 + j;   // float2 index of w=2j
    const int cs = C4 * plane2;                    // subband stride (float2)

    // 4 independent dense loads (one float2 per subband: w=2j, 2j+1)
    float2 ll = __ldcs(&x[base]);
    float2 lh = __ldcs(&x[base + cs]);
    float2 hl = __ldcs(&x[base + 2 * cs]);
    float2 hh = __ldcs(&x[base + 3 * cs]);

    // butterfly for the two input w positions
    float4 top, bot;
    {
        float a, bb, cc, d;
        a = ll.x; bb = lh.x; cc = hl.x; d = hh.x;
        top.x = 0.5f*(a+bb+cc+d);  top.y = 0.5f*(a+bb-cc-d);
        bot.x = 0.5f*(a-bb+cc-d);  bot.y = 0.5f*(a-bb-cc+d);
        a = ll.y; bb = lh.y; cc = hl.y; d = hh.y;
        top.z = 0.5f*(a+bb+cc+d);  top.w = 0.5f*(a+bb-cc-d);
        bot.z = 0.5f*(a-bb+cc-d);  bot.w = 0.5f*(a-bb-cc+d);
    }

    // output: 256 rows * 64 float4/row per (b,c) plane; rows 2h (top), 2h+1 (bot)
    int otop = (bc * 256 + 2 * h) * 64 + j;
    __stcs(&out[otop],      top);   // dense across warp: lane j -> f4 j
    __stcs(&out[otop + 64], bot);
}

extern "C" void kernel_launch(void* const* d_in, const int* in_sizes, int n_in,
                              void* d_out, int out_size)
{
    const float2* x = (const float2*)d_in[0];
    float4* out = (float4*)d_out;

    int total_threads = B * C4 * H * J;  // 8*64*128*64 = 4,194,304
    int block = 256;
    int grid = total_threads / block;    // 16384
    wav_unpack_kernel<<<grid, block>>>(x, out);
}